// round 1
// baseline (speedup 1.0000x reference)
#include <cuda_runtime.h>
#include <math.h>
#include <float.h>

// ---------------- problem constants ----------------
#define NIMG 4
#define H 128
#define W 128
#define P 11
#define KSEL 16
#define WIN 65          // search window
#define V 32            // WIN/2
#define S 3             // ref stride
#define HREF 40
#define WREF 40
#define LGRP (HREF*WREF)    // 1600 groups per image
#define WP 118              // H - P + 1 (patch-grid width)
#define NPIX (H*W)
#define NPATCH (P*P)        // 121
#define TILE 75             // WIN + P - 1
#define E_REG 30.25f        // n * alpha^2 * sigma^2 = 121*0.25
#define DE_REG 151.25f      // D + E = 121 + 30.25

// ---------------- device scratch (no allocs allowed) ----------------
__device__ float g_norm2[NIMG * WP * WP];
__device__ int   g_ind[NIMG * LGRP * KSEL];
__device__ float g_num[NIMG * NPIX];
__device__ float g_den[NIMG * NPIX];

// ---------------- zero accumulators ----------------
__global__ void zero_kernel() {
    int i = blockIdx.x * blockDim.x + threadIdx.x;
    if (i < NIMG * NPIX) { g_num[i] = 0.f; g_den[i] = 0.f; }
}

// ---------------- per-position patch squared norms ----------------
__global__ void norms_kernel(const float* __restrict__ y) {
    int idx = blockIdx.x * blockDim.x + threadIdx.x;
    if (idx >= NIMG * WP * WP) return;
    int n = idx / (WP * WP);
    int rc = idx % (WP * WP);
    int r = rc / WP, c = rc % WP;
    const float* img = y + n * NPIX;
    float s = 0.f;
#pragma unroll
    for (int a = 0; a < P; a++) {
#pragma unroll
        for (int b = 0; b < P; b++) {
            float v = __ldg(&img[(r + a) * W + c + b]);
            s += v * v;
        }
    }
    g_norm2[idx] = s;
}

// ---------------- block matching + top-16 ----------------
// one block per reference patch; 256 threads
__global__ __launch_bounds__(256) void bm_kernel(const float* __restrict__ y) {
    __shared__ float tile[TILE][TILE + 1];   // 75x76 padded window
    __shared__ float dist[WIN * WIN];        // 4225 candidate distances
    __shared__ float rmin[8];
    __shared__ int   rarg[8];

    const int n  = blockIdx.y;
    const int ih = blockIdx.x / WREF;
    const int iw = blockIdx.x % WREF;
    const int hr = ih * S;
    const int wr = iw * S;
    const float* img = y + n * NPIX;
    const int tid = threadIdx.x;

    // load 75x75 window (zero padded outside image)
    for (int i = tid; i < TILE * TILE; i += 256) {
        int a = i / TILE, b = i % TILE;
        int gr = hr - V + a, gc = wr - V + b;
        float v = 0.f;
        if (gr >= 0 && gr < H && gc >= 0 && gc < W) v = img[gr * W + gc];
        tile[a][b] = v;
    }
    __syncthreads();

    // cross-correlation with 5-wide dx register blocking: 65 dy * 13 groups
    for (int item = tid; item < WIN * 13; item += 256) {
        int dy  = item / 13;
        int grp = item % 13;
        int dx0 = grp * 5;
        float acc0 = 0.f, acc1 = 0.f, acc2 = 0.f, acc3 = 0.f, acc4 = 0.f;
#pragma unroll
        for (int a = 0; a < P; a++) {
            const float* crow = &tile[dy + a][dx0];
            const float* rrow = &tile[V + a][V];
            float c[P + 4];
#pragma unroll
            for (int t = 0; t < P + 4; t++) c[t] = crow[t];
#pragma unroll
            for (int b = 0; b < P; b++) {
                float r = rrow[b];
                acc0 += c[b]     * r;
                acc1 += c[b + 1] * r;
                acc2 += c[b + 2] * r;
                acc3 += c[b + 3] * r;
                acc4 += c[b + 4] * r;
            }
        }
        float accs[5] = {acc0, acc1, acc2, acc3, acc4};
        int baseR = hr + dy - V;                  // candidate patch row
        bool rok = (baseR >= 0) && (baseR <= H - P);
        const float* nrow = &g_norm2[(n * WP + (rok ? baseR : 0)) * WP];
#pragma unroll
        for (int j = 0; j < 5; j++) {
            int dx = dx0 + j;
            int cc = wr + dx - V;                 // candidate patch col
            float d = FLT_MAX;
            if (rok && cc >= 0 && cc <= W - P)
                d = nrow[cc] - 2.f * accs[j];     // ||c||^2 - 2<c,r>  (monotone in true dist)
            dist[dy * WIN + dx] = d;
        }
    }
    __syncthreads();
    if (tid == 0) dist[V * WIN + V] = -FLT_MAX;   // reference patch always kept first
    __syncthreads();

    // select 16 smallest (set semantics only; order is irrelevant downstream)
    int* out = &g_ind[(n * LGRP + blockIdx.x) * KSEL];
    for (int sel = 0; sel < KSEL; sel++) {
        float bv = FLT_MAX; int bi = WIN * WIN;
        for (int o = tid; o < WIN * WIN; o += 256) {
            float v = dist[o];
            if (v < bv || (v == bv && o < bi)) { bv = v; bi = o; }
        }
#pragma unroll
        for (int off = 16; off > 0; off >>= 1) {
            float ov = __shfl_down_sync(0xffffffffu, bv, off);
            int   oi = __shfl_down_sync(0xffffffffu, bi, off);
            if (ov < bv || (ov == bv && oi < bi)) { bv = ov; bi = oi; }
        }
        if ((tid & 31) == 0) { rmin[tid >> 5] = bv; rarg[tid >> 5] = bi; }
        __syncthreads();
        if (tid == 0) {
            float fv = rmin[0]; int fi = rarg[0];
            for (int w = 1; w < 8; w++) {
                if (rmin[w] < fv || (rmin[w] == fv && rarg[w] < fi)) { fv = rmin[w]; fi = rarg[w]; }
            }
            int dy = fi / WIN, dx = fi % WIN;
            int rr = hr + dy - V, cc = wr + dx - V;
            out[sel] = rr * WP + cc;
            dist[fi] = FLT_MAX;                  // remove from further selection
        }
        __syncthreads();
    }
}

// ---------------- gather + denoise + scatter ----------------
// one block per group; 128 threads
__global__ __launch_bounds__(128) void denoise_kernel(const float* __restrict__ y) {
    __shared__ float Ys[KSEL][NPATCH + 3];   // 16 x 124
    __shared__ float Qs[KSEL][KSEL + 1];     // Q, then Cholesky factor L in lower tri
    __shared__ float Qi[KSEL][KSEL + 1];     // Q^{-1}
    __shared__ float Th[KSEL][KSEL + 1];     // theta (symmetric)
    __shared__ float wgt[KSEL];
    __shared__ float q1[KSEL];
    __shared__ float q2s;
    __shared__ int   pr[KSEL], pc[KSEL];

    const int g = blockIdx.x;
    const int n = g / LGRP;
    const int tid = threadIdx.x;
    const float* img = y + n * NPIX;

    if (tid < KSEL) {
        int idx = g_ind[g * KSEL + tid];
        pr[tid] = idx / WP;
        pc[tid] = idx % WP;
    }
    __syncthreads();

    // gather Y (16 patches x 121 pixels)
    for (int t = tid; t < KSEL * NPATCH; t += 128) {
        int i = t / NPATCH, e = t % NPATCH;
        int a = e / P, b = e % P;
        Ys[i][e] = img[(pr[i] + a) * W + pc[i] + b];
    }
    __syncthreads();

    // Q = Y Y^T + E I
    for (int t = tid; t < KSEL * KSEL; t += 128) {
        int i = t / KSEL, j = t % KSEL;
        float s = 0.f;
        for (int e = 0; e < NPATCH; e++) s += Ys[i][e] * Ys[j][e];
        if (i == j) s += E_REG;
        Qs[i][j] = s;
    }
    __syncthreads();

    // Cholesky + inverse on warp 0
    if (tid < 32) {
        int lane = tid;
        for (int j = 0; j < KSEL; j++) {
            if (lane == 0) Qs[j][j] = sqrtf(Qs[j][j]);
            __syncwarp();
            float dj = Qs[j][j];
            if (lane > j && lane < KSEL) Qs[lane][j] /= dj;
            __syncwarp();
            if (lane > j && lane < KSEL) {
                float lij = Qs[lane][j];
                for (int m = j + 1; m <= lane; m++) Qs[lane][m] -= lij * Qs[m][j];
            }
            __syncwarp();
        }
        if (lane < KSEL) {
            float z[KSEL];
            // forward: L z = e_lane
            for (int i = 0; i < KSEL; i++) {
                float s = (i == lane) ? 1.f : 0.f;
                for (int j = 0; j < i; j++) s -= Qs[i][j] * z[j];
                z[i] = s / Qs[i][i];
            }
            // backward: L^T x = z
            for (int i = KSEL - 1; i >= 0; i--) {
                float s = z[i];
                for (int j = i + 1; j < KSEL; j++) s -= Qs[j][i] * z[j];
                z[i] = s / Qs[i][i];
            }
            for (int i = 0; i < KSEL; i++) Qi[i][lane] = z[i];
        }
    }
    __syncthreads();

    // theta = I - (Qinv - q1 q1^T / q2) * (D+E)   (symmetric)
    if (tid < KSEL) {
        float s = 0.f;
        for (int j = 0; j < KSEL; j++) s += Qi[tid][j];
        q1[tid] = s;
    }
    __syncthreads();
    if (tid == 0) {
        float s = 0.f;
        for (int i = 0; i < KSEL; i++) s += q1[i];
        q2s = s;
    }
    __syncthreads();
    for (int t = tid; t < KSEL * KSEL; t += 128) {
        int i = t / KSEL, j = t % KSEL;
        float v = ((i == j) ? 1.f : 0.f) - (Qi[i][j] - q1[i] * q1[j] / q2s) * DE_REG;
        Th[i][j] = v;
    }
    __syncthreads();
    if (tid < KSEL) {
        float s = 0.f;
        for (int j = 0; j < KSEL; j++) s += Th[tid][j] * Th[tid][j];
        s = fminf(fmaxf(s, 1.f / (float)KSEL), 1.f);
        wgt[tid] = 1.f / s;
    }
    __syncthreads();

    // X_hat = theta @ Y ; scatter weighted patches + weights
    float* numI = g_num + n * NPIX;
    float* denI = g_den + n * NPIX;
    for (int t = tid; t < KSEL * NPATCH; t += 128) {
        int i = t / NPATCH, e = t % NPATCH;
        float s = 0.f;
#pragma unroll
        for (int j = 0; j < KSEL; j++) s += Th[i][j] * Ys[j][e];
        float wv = wgt[i];
        int a = e / P, b = e % P;
        int pix = (pr[i] + a) * W + pc[i] + b;
        atomicAdd(&numI[pix], s * wv);
        atomicAdd(&denI[pix], wv);
    }
}

// ---------------- final divide ----------------
__global__ void div_kernel(float* __restrict__ out) {
    int i = blockIdx.x * blockDim.x + threadIdx.x;
    if (i < NIMG * NPIX) out[i] = g_num[i] / g_den[i];
}

extern "C" void kernel_launch(void* const* d_in, const int* in_sizes, int n_in,
                              void* d_out, int out_size) {
    const float* y = (const float*)d_in[0];
    float* out = (float*)d_out;

    zero_kernel<<<(NIMG * NPIX + 255) / 256, 256>>>();
    norms_kernel<<<(NIMG * WP * WP + 127) / 128, 128>>>(y);

    dim3 bmgrid(LGRP, NIMG);
    bm_kernel<<<bmgrid, 256>>>(y);

    denoise_kernel<<<NIMG * LGRP, 128>>>(y);

    div_kernel<<<(NIMG * NPIX + 255) / 256, 256>>>(out);
}